// round 16
// baseline (speedup 1.0000x reference)
#include <cuda_runtime.h>
#include <cuda_fp16.h>
#include <stdint.h>
#include <math.h>

// ---------------- problem constants ----------------
#define DMODEL 768
#define NHEADS 12
#define DHEAD  64
#define DFF    3072
#define BBATCH 2
#define TSEQ   4096
#define MTOK   (BBATCH * TSEQ)   // 8192 tokens

// weight (transposed [N,K], fp16) offsets inside g_w
#define WQ_OFF 0
#define WO_OFF (3*768*768)
#define W1_OFF (4*768*768)                 // [3072][768]
#define W2_OFF (4*768*768 + 768*3072)      // [768][3072]
#define WTOT   (4*768*768 + 2*768*3072)

// ---------------- scratch (device globals; no allocation allowed) ----------------
__device__ float g_R1 [MTOK * DMODEL];
__device__ float g_H  [MTOK * DMODEL];
__device__ float g_R2 [MTOK * DMODEL];
__device__ __half g_qh [MTOK * DMODEL];
__device__ __half g_kh [MTOK * DMODEL];
__device__ __half g_vh [MTOK * DMODEL];
__device__ __half g_act[MTOK * DMODEL];
__device__ __half g_ff [MTOK * DFF];
__device__ __half g_w  [WTOT];

// ---------------- helpers ----------------
__device__ __forceinline__ uint32_t smem_u32(const void* p) {
    uint32_t a;
    asm("{ .reg .u64 t; cvta.to.shared.u64 t, %1; cvt.u32.u64 %0, t; }" : "=r"(a) : "l"(p));
    return a;
}
__device__ __forceinline__ void cp16(uint32_t d, const void* s) {
    asm volatile("cp.async.cg.shared.global [%0], [%1], 16;" :: "r"(d), "l"(s));
}
#define CP_COMMIT() asm volatile("cp.async.commit_group;" ::: "memory")
#define CP_WAIT1()  asm volatile("cp.async.wait_group 1;"  ::: "memory")

#define LDSM4(r0, r1, r2, r3, addr) \
    asm volatile("ldmatrix.sync.aligned.m8n8.x4.shared.b16 {%0,%1,%2,%3}, [%4];" \
        : "=r"(r0), "=r"(r1), "=r"(r2), "=r"(r3) : "r"(addr))
#define LDSM4T(r0, r1, r2, r3, addr) \
    asm volatile("ldmatrix.sync.aligned.m8n8.x4.trans.shared.b16 {%0,%1,%2,%3}, [%4];" \
        : "=r"(r0), "=r"(r1), "=r"(r2), "=r"(r3) : "r"(addr))

#define MMA16816(c, a, b) \
    asm volatile("mma.sync.aligned.m16n8k16.row.col.f32.f16.f16.f32 " \
        "{%0,%1,%2,%3},{%4,%5,%6,%7},{%8,%9},{%0,%1,%2,%3};" \
        : "+f"((c)[0]), "+f"((c)[1]), "+f"((c)[2]), "+f"((c)[3]) \
        : "r"((a)[0]), "r"((a)[1]), "r"((a)[2]), "r"((a)[3]), \
          "r"((b)[0]), "r"((b)[1]))

__device__ __forceinline__ uint32_t pack2h(float a, float b) {
    __half2 h = __floats2half2_rn(a, b);
    return *(uint32_t*)&h;
}

// =================================================================
// mma.sync GEMM (pure fp16), templated on BN tile (128 or 64).
// C = A @ Bt^T (+bias)(+res)(+relu); fp32 accum; BK=32; 256 threads;
// 3-stage cp.async ring, one __syncthreads per k-step.
// BN=128: 8 warps as 2(m)x4(n), warp 64x32, acc[4][4][4].
// BN=64 : 8 warps as 4(m)x2(n), warp 32x32, acc[2][4][4].
// qkv mode (BN=128 only callers) splits output cols into 3 dests.
// =================================================================
#define BKG   32
#define ROWB  80
#define TILEB 10240                     // 128 A-rows * 80B

template<int BN_T>
__device__ __forceinline__ void load_stage_t(
    uint32_t st, const __half* A, const __half* B,
    int bm, int bn, int k0, int K, int tid)
{
    constexpr int NLD = (128 + BN_T) / 64;     // cp16 per thread
#pragma unroll
    for (int i = 0; i < NLD; i++) {
        int idx = tid + i * 256;
        int r   = idx >> 2;                    // 0..(128+BN_T-1)
        int kc  = (idx & 3) * 8;
        if (r < 128) {
            cp16(st + (uint32_t)(r * ROWB + kc * 2),
                 A + (size_t)(bm + r) * K + k0 + kc);
        } else {
            int rb = r - 128;
            cp16(st + TILEB + (uint32_t)(rb * ROWB + kc * 2),
                 B + (size_t)(bn + rb) * K + k0 + kc);
        }
    }
}

template<int BN_T>
__global__ __launch_bounds__(256, 2)
void gemm_mma(const __half* __restrict__ A, const __half* __restrict__ B,
              const float* __restrict__ bias, const float* __restrict__ res,
              float* __restrict__ C, __half* __restrict__ Chf,
              int N, int K, int relu, int qkv,
              const float* __restrict__ bias1, const float* __restrict__ bias2,
              __half* __restrict__ Chf1, __half* __restrict__ Chf2)
{
    constexpr int MT = (BN_T == 128) ? 4 : 2;              // m-frags per warp
    constexpr uint32_t STG = (uint32_t)(128 + BN_T) * ROWB; // stage bytes

    extern __shared__ char smem[];
    const uint32_t sb = smem_u32(smem);
    const int tid = threadIdx.x;
    const int wid = tid >> 5, lane = tid & 31;
    const int wm = (BN_T == 128) ? (wid & 1) : (wid & 3);
    const int wn = (BN_T == 128) ? (wid >> 1) : (wid >> 2);
    const int moff = wm * (16 * MT);
    const int bm = blockIdx.y * 128, bn = blockIdx.x * BN_T;

    float acc[MT][4][4];
#pragma unroll
    for (int mt = 0; mt < MT; mt++)
#pragma unroll
        for (int nt = 0; nt < 4; nt++)
#pragma unroll
            for (int i = 0; i < 4; i++) acc[mt][nt][i] = 0.f;

    const int nk = K / BKG;
    load_stage_t<BN_T>(sb, A, B, bm, bn, 0, K, tid);
    CP_COMMIT();
    load_stage_t<BN_T>(sb + STG, A, B, bm, bn, BKG, K, tid);
    CP_COMMIT();

    for (int ks = 0; ks < nk; ks++) {
        CP_WAIT1();
        __syncthreads();
        if (ks + 2 < nk)
            load_stage_t<BN_T>(sb + ((ks + 2) % 3) * STG, A, B, bm, bn,
                               (ks + 2) * BKG, K, tid);
        CP_COMMIT();

        const uint32_t st = sb + (ks % 3) * STG;
#pragma unroll
        for (int kk = 0; kk < 2; kk++) {
            uint32_t af[MT][4];
            uint32_t aoff = st + (uint32_t)((moff + (lane & 15)) * ROWB)
                          + kk * 32 + ((lane >> 4) & 1) * 16;
#pragma unroll
            for (int mt = 0; mt < MT; mt++)
                LDSM4(af[mt][0], af[mt][1], af[mt][2], af[mt][3], aoff + mt * 16 * ROWB);

            uint32_t bf[4][2];
            uint32_t boff = st + TILEB
                          + (uint32_t)((wn * 32 + (lane & 7) + ((lane >> 4) & 1) * 8) * ROWB)
                          + kk * 32 + ((lane >> 3) & 1) * 16;
#pragma unroll
            for (int np = 0; np < 2; np++) {
                uint32_t r0, r1, r2, r3;
                LDSM4(r0, r1, r2, r3, boff + np * 16 * ROWB);
                bf[2*np][0] = r0; bf[2*np][1] = r1; bf[2*np+1][0] = r2; bf[2*np+1][1] = r3;
            }
#pragma unroll
            for (int mt = 0; mt < MT; mt++)
#pragma unroll
                for (int nt = 0; nt < 4; nt++)
                    MMA16816(acc[mt][nt], af[mt], bf[nt]);
        }
    }
    __syncthreads();

    // ---- epilogue (qkv mode: route by output-column segment) ----
    int bnl = bn, Nol = N;
    const float* bi = bias;
    __half* dst = Chf;
    if (qkv) {
        int seg = bn / 768;
        bnl = bn - seg * 768;
        Nol = 768;
        bi  = (seg == 0) ? bias : (seg == 1) ? bias1 : bias2;
        dst = (seg == 0) ? Chf  : (seg == 1) ? Chf1  : Chf2;
    }

#pragma unroll
    for (int mt = 0; mt < MT; mt++)
#pragma unroll
        for (int nt = 0; nt < 4; nt++) {
            int row = bm + moff + mt * 16 + (lane >> 2);
            int col = bnl + wn * 32 + nt * 8 + (lane & 3) * 2;
            float b0 = bi[col], b1 = bi[col + 1];
#pragma unroll
            for (int half = 0; half < 2; half++) {
                int r = row + half * 8;
                size_t idx = (size_t)r * Nol + col;
                float v0 = acc[mt][nt][half * 2 + 0] + b0;
                float v1 = acc[mt][nt][half * 2 + 1] + b1;
                if (res) {
                    float2 rv = *(const float2*)&res[idx];
                    v0 += rv.x; v1 += rv.y;
                }
                if (relu) { v0 = fmaxf(v0, 0.f); v1 = fmaxf(v1, 0.f); }
                if (C) { float2 o = make_float2(v0, v1); *(float2*)&C[idx] = o; }
                if (dst) *(__half2*)&dst[idx] = __floats2half2_rn(v0, v1);
            }
        }
}

#define GEMM_SMEM_128 (3 * (128 + 128) * ROWB)   // 61440
#define GEMM_SMEM_64  (3 * (128 + 64)  * ROWB)   // 46080

// =================================================================
// Fused weight transpose: all 6 matrices in ONE launch.
// blocks [0,2304): wq/wk/wv/wo (576 tiles each, 24x24)
// blocks [2304,4608): w1 (768x3072 -> 24 k-tiles x 96 n-tiles)
// blocks [4608,6912): w2 (3072x768 -> 96 k-tiles x 24 n-tiles)
// =================================================================
__global__ void wsplit_all(const float* __restrict__ wq, const float* __restrict__ wk,
                           const float* __restrict__ wv, const float* __restrict__ wo,
                           const float* __restrict__ w1, const float* __restrict__ w2,
                           __half* __restrict__ Wd)
{
    __shared__ float t[32][33];
    int bidx = blockIdx.x;
    const float* W; __half* T; int Kd, Nd, kt, nt;
    if (bidx < 2304) {
        int m = bidx / 576, tile = bidx % 576;
        W = (m == 0) ? wq : (m == 1) ? wk : (m == 2) ? wv : wo;
        T = Wd + (size_t)m * 768 * 768;
        Kd = 768; Nd = 768; kt = tile % 24; nt = tile / 24;
    } else if (bidx < 4608) {
        int tile = bidx - 2304;
        W = w1; T = Wd + W1_OFF;
        Kd = 768; Nd = 3072; kt = tile % 24; nt = tile / 24;
    } else {
        int tile = bidx - 4608;
        W = w2; T = Wd + W2_OFF;
        Kd = 3072; Nd = 768; kt = tile % 96; nt = tile / 96;
    }
    int k0 = kt * 32, n0 = nt * 32;
    int tx = threadIdx.x, ty = threadIdx.y;
    for (int i = ty; i < 32; i += 8)
        t[i][tx] = W[(size_t)(k0 + i) * Nd + n0 + tx];
    __syncthreads();
    for (int i = ty; i < 32; i += 8)
        T[(size_t)(n0 + i) * Kd + k0 + tx] = __float2half_rn(t[tx][i]);
}

// activation fp32 -> fp16
__global__ void asplit_kernel(const float* __restrict__ A, __half* __restrict__ Ah)
{
    int i = (blockIdx.x * blockDim.x + threadIdx.x) * 4;
    float4 v = *(const float4*)&A[i];
    *(__half2*)&Ah[i]     = __floats2half2_rn(v.x, v.y);
    *(__half2*)&Ah[i + 2] = __floats2half2_rn(v.z, v.w);
}

// =================================================================
// Flash attention (causal) on mma.sync, pure fp16, fp32 softmax.
// 128 queries x (head,batch); 8 warps; 64-key chunks; 3-stage cp.async ring.
// Occupancy 2.
// =================================================================
#define APITCH   144
#define AST_OFF  18432               // Q: 128*144
#define AVH 9216
#define AST_SZ   18432               // K + V tiles
#define ATT_SMEM (AST_OFF + 3 * AST_SZ)   // 73728 B

__device__ __forceinline__ void att_load_kv(
    uint32_t stbase, const __half* Kh, const __half* Vh,
    int b, int h, int j0, int tid)
{
#pragma unroll
    for (int i = 0; i < 4; i++) {
        int idx = tid + i * 256;          // 0..1023
        int t   = idx >> 9;               // 0=K 1=V
        int rem = idx & 511;
        int r   = rem >> 3;               // row 0..63
        int c   = (rem & 7) * 8;
        size_t go = (size_t)(b * TSEQ + j0 + r) * DMODEL + h * DHEAD + c;
        cp16(stbase + t * AVH + r * APITCH + c * 2, (t ? Vh : Kh) + go);
    }
}

__global__ __launch_bounds__(256, 2)
void attn_mma(const __half* __restrict__ Qh,
              const __half* __restrict__ Kh, const __half* __restrict__ Vh,
              __half* __restrict__ Oh)
{
    extern __shared__ char smem[];
    const uint32_t sb = smem_u32(smem);
    const int tid = threadIdx.x;
    const int wid = tid >> 5, lane = tid & 31;
    const int q0 = (gridDim.x - 1 - blockIdx.x) * 128;   // long blocks first
    const int h  = blockIdx.y;
    const int b  = blockIdx.z;

    // ---- load Q tile ----
#pragma unroll
    for (int i = 0; i < 4; i++) {
        int idx = tid + i * 256;
        int r   = idx >> 3;
        int c   = (idx & 7) * 8;
        size_t go = (size_t)(b * TSEQ + q0 + r) * DMODEL + h * DHEAD + c;
        cp16(sb + r * APITCH + c * 2, Qh + go);
    }
    CP_COMMIT();

    const int nch = q0 / 64 + 2;      // >= 2 always
    att_load_kv(sb + AST_OFF, Kh, Vh, b, h, 0, tid);
    CP_COMMIT();
    att_load_kv(sb + AST_OFF + AST_SZ, Kh, Vh, b, h, 64, tid);
    CP_COMMIT();

    float m2[2] = {-1e30f, -1e30f};
    float l2[2] = {0.f, 0.f};
    float o[8][4];
#pragma unroll
    for (int nt = 0; nt < 8; nt++)
#pragma unroll
        for (int i = 0; i < 4; i++) o[nt][i] = 0.f;

    const int r0g = q0 + wid * 16 + (lane >> 2);

    for (int ci = 0; ci < nch; ci++) {
        CP_WAIT1();
        __syncthreads();
        if (ci + 2 < nch)
            att_load_kv(sb + AST_OFF + ((ci + 2) % 3) * AST_SZ,
                        Kh, Vh, b, h, (ci + 2) * 64, tid);
        CP_COMMIT();

        const uint32_t st = sb + AST_OFF + (ci % 3) * AST_SZ;
        const int j0 = ci * 64;

        // ---- S = Q K^T ----
        float s[8][4];
#pragma unroll
        for (int nt = 0; nt < 8; nt++)
#pragma unroll
            for (int i = 0; i < 4; i++) s[nt][i] = 0.f;

#pragma unroll
        for (int kk = 0; kk < 4; kk++) {
            uint32_t qa[4];
            uint32_t aoff = sb + (uint32_t)((wid * 16 + (lane & 15)) * APITCH)
                          + kk * 32 + ((lane >> 4) & 1) * 16;
            LDSM4(qa[0], qa[1], qa[2], qa[3], aoff);
#pragma unroll
            for (int np = 0; np < 4; np++) {
                uint32_t boff = st
                              + (uint32_t)((np * 16 + (lane & 7) + ((lane >> 4) & 1) * 8) * APITCH)
                              + kk * 32 + ((lane >> 3) & 1) * 16;
                uint32_t k0r, k1r, k2r, k3r;
                LDSM4(k0r, k1r, k2r, k3r, boff);
                uint32_t bh0[2] = {k0r, k1r}, bh1[2] = {k2r, k3r};
                MMA16816(s[2*np],   qa, bh0);
                MMA16816(s[2*np+1], qa, bh1);
            }
        }

        // ---- scale + causal mask ----
#pragma unroll
        for (int nt = 0; nt < 8; nt++)
#pragma unroll
            for (int i = 0; i < 4; i++) s[nt][i] *= 0.125f;

        if (j0 >= q0) {
#pragma unroll
            for (int nt = 0; nt < 8; nt++) {
                int col = j0 + nt * 8 + (lane & 3) * 2;
                if (col     > r0g)     s[nt][0] = -1e30f;
                if (col + 1 > r0g)     s[nt][1] = -1e30f;
                if (col     > r0g + 8) s[nt][2] = -1e30f;
                if (col + 1 > r0g + 8) s[nt][3] = -1e30f;
            }
        }

        // ---- streaming softmax ----
#pragma unroll
        for (int rh = 0; rh < 2; rh++) {
            float cm = -1e30f;
#pragma unroll
            for (int nt = 0; nt < 8; nt++)
                cm = fmaxf(cm, fmaxf(s[nt][rh*2], s[nt][rh*2+1]));
            cm = fmaxf(cm, __shfl_xor_sync(0xffffffffu, cm, 1));
            cm = fmaxf(cm, __shfl_xor_sync(0xffffffffu, cm, 2));
            float mn = fmaxf(m2[rh], cm);
            float corr = __expf(m2[rh] - mn);
            m2[rh] = mn;
            float rs = 0.f;
#pragma unroll
            for (int nt = 0; nt < 8; nt++) {
                float p0 = __expf(s[nt][rh*2]   - mn);
                float p1 = __expf(s[nt][rh*2+1] - mn);
                s[nt][rh*2] = p0; s[nt][rh*2+1] = p1;
                rs += p0 + p1;
            }
            rs += __shfl_xor_sync(0xffffffffu, rs, 1);
            rs += __shfl_xor_sync(0xffffffffu, rs, 2);
            l2[rh] = l2[rh] * corr + rs;
#pragma unroll
            for (int nt = 0; nt < 8; nt++) {
                o[nt][rh*2]   *= corr;
                o[nt][rh*2+1] *= corr;
            }
        }

        // ---- O += P V ----
#pragma unroll
        for (int kc = 0; kc < 4; kc++) {
            uint32_t ph[4];
            ph[0] = pack2h(s[2*kc][0],   s[2*kc][1]);
            ph[1] = pack2h(s[2*kc][2],   s[2*kc][3]);
            ph[2] = pack2h(s[2*kc+1][0], s[2*kc+1][1]);
            ph[3] = pack2h(s[2*kc+1][2], s[2*kc+1][3]);
#pragma unroll
            for (int np = 0; np < 4; np++) {
                uint32_t voff = st + AVH
                              + (uint32_t)((kc * 16 + (lane & 15)) * APITCH)
                              + (np * 16 + ((lane >> 4) & 1) * 8) * 2;
                uint32_t v0r, v1r, v2r, v3r;
                LDSM4T(v0r, v1r, v2r, v3r, voff);
                uint32_t vh0[2] = {v0r, v1r}, vh1[2] = {v2r, v3r};
                MMA16816(o[2*np],   ph, vh0);
                MMA16816(o[2*np+1], ph, vh1);
            }
        }
    }

    // ---- normalize + write fp16 ----
    float inv0 = 1.f / l2[0], inv1 = 1.f / l2[1];
#pragma unroll
    for (int nt = 0; nt < 8; nt++) {
        int col = h * DHEAD + nt * 8 + (lane & 3) * 2;
        size_t i0 = (size_t)(b * TSEQ + r0g) * DMODEL + col;
        size_t i1 = (size_t)(b * TSEQ + r0g + 8) * DMODEL + col;
        *(__half2*)&Oh[i0] = __floats2half2_rn(o[nt][0] * inv0, o[nt][1] * inv0);
        *(__half2*)&Oh[i1] = __floats2half2_rn(o[nt][2] * inv1, o[nt][3] * inv1);
    }
}

// =================================================================
// LayerNorm; optionally also emits fp16 of the output.
// =================================================================
__global__ __launch_bounds__(256)
void ln_kernel(const float* __restrict__ in, const float* __restrict__ g,
               const float* __restrict__ be, float* __restrict__ out,
               __half* __restrict__ Oh)
{
    const int row = blockIdx.x;
    const int tid = threadIdx.x;
    const float* xr = in + (size_t)row * DMODEL;

    float v0 = xr[tid], v1 = xr[tid + 256], v2 = xr[tid + 512];
    float s = v0 + v1 + v2;
    float s2 = v0 * v0 + v1 * v1 + v2 * v2;

    __shared__ float rs[8], rs2[8], stats[2];
#pragma unroll
    for (int off = 16; off; off >>= 1) {
        s  += __shfl_xor_sync(0xffffffffu, s,  off);
        s2 += __shfl_xor_sync(0xffffffffu, s2, off);
    }
    int w = tid >> 5, lane = tid & 31;
    if (lane == 0) { rs[w] = s; rs2[w] = s2; }
    __syncthreads();
    if (tid == 0) {
        float S = 0.f, S2 = 0.f;
#pragma unroll
        for (int i = 0; i < 8; i++) { S += rs[i]; S2 += rs2[i]; }
        float mean = S * (1.f / DMODEL);
        float var  = S2 * (1.f / DMODEL) - mean * mean;
        stats[0] = mean;
        stats[1] = rsqrtf(var + 1e-5f);
    }
    __syncthreads();
    float mean = stats[0], r = stats[1];
    size_t rb = (size_t)row * DMODEL;
    float vv[3] = {v0, v1, v2};
#pragma unroll
    for (int p = 0; p < 3; p++) {
        int c = tid + p * 256;
        float y = (vv[p] - mean) * r * g[c] + be[c];
        out[rb + c] = y;
        if (Oh) Oh[rb + c] = __float2half_rn(y);
    }
}

// =================================================================
// Host launch
// =================================================================
extern "C" void kernel_launch(void* const* d_in, const int* in_sizes, int n_in,
                              void* d_out, int out_size)
{
    const float* x  = (const float*)d_in[0];
    const float* wq = (const float*)d_in[1];
    const float* bq = (const float*)d_in[2];
    const float* wk = (const float*)d_in[3];
    const float* bk = (const float*)d_in[4];
    const float* wv = (const float*)d_in[5];
    const float* bv = (const float*)d_in[6];
    const float* wo = (const float*)d_in[7];
    const float* bo = (const float*)d_in[8];
    const float* w1 = (const float*)d_in[9];
    const float* b1 = (const float*)d_in[10];
    const float* w2 = (const float*)d_in[11];
    const float* b2 = (const float*)d_in[12];
    const float* g1 = (const float*)d_in[13];
    const float* be1= (const float*)d_in[14];
    const float* g2 = (const float*)d_in[15];
    const float* be2= (const float*)d_in[16];
    float* out = (float*)d_out;

    float *R1, *H, *R2;
    __half *Qh, *Kh, *Vh, *Act, *FF, *W;
    cudaGetSymbolAddress((void**)&R1,  g_R1);
    cudaGetSymbolAddress((void**)&H,   g_H);
    cudaGetSymbolAddress((void**)&R2,  g_R2);
    cudaGetSymbolAddress((void**)&Qh,  g_qh);
    cudaGetSymbolAddress((void**)&Kh,  g_kh);
    cudaGetSymbolAddress((void**)&Vh,  g_vh);
    cudaGetSymbolAddress((void**)&Act, g_act);
    cudaGetSymbolAddress((void**)&FF,  g_ff);
    cudaGetSymbolAddress((void**)&W,   g_w);

    cudaFuncSetAttribute(attn_mma, cudaFuncAttributeMaxDynamicSharedMemorySize, ATT_SMEM);
    cudaFuncSetAttribute(gemm_mma<128>, cudaFuncAttributeMaxDynamicSharedMemorySize, GEMM_SMEM_128);
    cudaFuncSetAttribute(gemm_mma<64>,  cudaFuncAttributeMaxDynamicSharedMemorySize, GEMM_SMEM_64);

    // all weight transposes in one launch
    wsplit_all<<<6912, dim3(32, 8)>>>(wq, wk, wv, wo, w1, w2, W);

    // x -> fp16
    asplit_kernel<<<MTOK * DMODEL / 1024, 256>>>(x, Act);

    dim3 gQKV((3 * DMODEL) / 128, MTOK / 128);  // (18, 64)
    dim3 gD64(DMODEL / 64, MTOK / 128);         // (12, 64)
    dim3 gF(DFF / 128,    MTOK / 128);          // (24, 64)

    // fused QKV projection (weights contiguous as [2304][768])
    gemm_mma<128><<<gQKV, 256, GEMM_SMEM_128>>>(Act, W + WQ_OFF, bq, nullptr, nullptr, Qh,
                                                3 * DMODEL, DMODEL, 0, 1, bk, bv, Kh, Vh);

    // causal flash attention -> attn out fp16 into Act
    attn_mma<<<dim3(TSEQ / 128, NHEADS, BBATCH), 256, ATT_SMEM>>>(Qh, Kh, Vh, Act);

    // output projection + residual(x), LN1 (emits H fp16 into Act)
    gemm_mma<64><<<gD64, 256, GEMM_SMEM_64>>>(Act, W + WO_OFF, bo, x, R1, nullptr,
                                              DMODEL, DMODEL, 0, 0, nullptr, nullptr, nullptr, nullptr);
    ln_kernel<<<MTOK, 256>>>(R1, g1, be1, H, Act);

    // FFN: W1 (+relu) -> FF fp16; W2 + residual(H)
    gemm_mma<128><<<gF, 256, GEMM_SMEM_128>>>(Act, W + W1_OFF, b1, nullptr, nullptr, FF,
                                              DFF, DMODEL, 1, 0, nullptr, nullptr, nullptr, nullptr);
    gemm_mma<64><<<gD64, 256, GEMM_SMEM_64>>>(FF,  W + W2_OFF, b2, H, R2, nullptr,
                                              DMODEL, DFF, 0, 0, nullptr, nullptr, nullptr, nullptr);

    // LN2 -> output
    ln_kernel<<<MTOK, 256>>>(R2, g2, be2, out, nullptr);
}

// round 17
// speedup vs baseline: 1.0169x; 1.0169x over previous
#include <cuda_runtime.h>
#include <cuda_fp16.h>
#include <stdint.h>
#include <math.h>

// ---------------- problem constants ----------------
#define DMODEL 768
#define NHEADS 12
#define DHEAD  64
#define DFF    3072
#define BBATCH 2
#define TSEQ   4096
#define MTOK   (BBATCH * TSEQ)   // 8192 tokens

// weight (transposed [N,K], fp16) offsets inside g_w
#define WQ_OFF 0
#define WO_OFF (3*768*768)
#define W1_OFF (4*768*768)                 // [3072][768]
#define W2_OFF (4*768*768 + 768*3072)      // [768][3072]
#define WTOT   (4*768*768 + 2*768*3072)

// ---------------- scratch (device globals; no allocation allowed) ----------------
__device__ float g_R1 [MTOK * DMODEL];
__device__ float g_H  [MTOK * DMODEL];
__device__ float g_R2 [MTOK * DMODEL];
__device__ __half g_qh [MTOK * DMODEL];
__device__ __half g_kh [MTOK * DMODEL];
__device__ __half g_vh [MTOK * DMODEL];
__device__ __half g_act[MTOK * DMODEL];
__device__ __half g_ff [MTOK * DFF];
__device__ __half g_w  [WTOT];

// ---------------- helpers ----------------
__device__ __forceinline__ uint32_t smem_u32(const void* p) {
    uint32_t a;
    asm("{ .reg .u64 t; cvta.to.shared.u64 t, %1; cvt.u32.u64 %0, t; }" : "=r"(a) : "l"(p));
    return a;
}
__device__ __forceinline__ void cp16(uint32_t d, const void* s) {
    asm volatile("cp.async.cg.shared.global [%0], [%1], 16;" :: "r"(d), "l"(s));
}
#define CP_COMMIT() asm volatile("cp.async.commit_group;" ::: "memory")
#define CP_WAIT1()  asm volatile("cp.async.wait_group 1;"  ::: "memory")

#define LDSM4(r0, r1, r2, r3, addr) \
    asm volatile("ldmatrix.sync.aligned.m8n8.x4.shared.b16 {%0,%1,%2,%3}, [%4];" \
        : "=r"(r0), "=r"(r1), "=r"(r2), "=r"(r3) : "r"(addr))
#define LDSM4T(r0, r1, r2, r3, addr) \
    asm volatile("ldmatrix.sync.aligned.m8n8.x4.trans.shared.b16 {%0,%1,%2,%3}, [%4];" \
        : "=r"(r0), "=r"(r1), "=r"(r2), "=r"(r3) : "r"(addr))

#define MMA16816(c, a, b) \
    asm volatile("mma.sync.aligned.m16n8k16.row.col.f32.f16.f16.f32 " \
        "{%0,%1,%2,%3},{%4,%5,%6,%7},{%8,%9},{%0,%1,%2,%3};" \
        : "+f"((c)[0]), "+f"((c)[1]), "+f"((c)[2]), "+f"((c)[3]) \
        : "r"((a)[0]), "r"((a)[1]), "r"((a)[2]), "r"((a)[3]), \
          "r"((b)[0]), "r"((b)[1]))

__device__ __forceinline__ uint32_t pack2h(float a, float b) {
    __half2 h = __floats2half2_rn(a, b);
    return *(uint32_t*)&h;
}

// =================================================================
// mma.sync GEMM (pure fp16), templated on BN tile (128 or 64).
// C = A @ Bt^T (+bias)(+res)(+relu); fp32 accum; BK=32; 256 threads;
// 3-stage cp.async ring, one __syncthreads per k-step.
// BN=128: 8 warps as 2(m)x4(n), warp 64x32, acc[4][4][4].
// BN=64 : 8 warps as 4(m)x2(n), warp 32x32, acc[2][4][4].
// qkv mode (BN=128 only callers) splits output cols into 3 dests.
// =================================================================
#define BKG   32
#define ROWB  80
#define TILEB 10240                     // 128 A-rows * 80B

template<int BN_T>
__device__ __forceinline__ void load_stage_t(
    uint32_t st, const __half* A, const __half* B,
    int bm, int bn, int k0, int K, int tid)
{
    constexpr int NLD = (128 + BN_T) / 64;     // cp16 per thread
#pragma unroll
    for (int i = 0; i < NLD; i++) {
        int idx = tid + i * 256;
        int r   = idx >> 2;                    // 0..(128+BN_T-1)
        int kc  = (idx & 3) * 8;
        if (r < 128) {
            cp16(st + (uint32_t)(r * ROWB + kc * 2),
                 A + (size_t)(bm + r) * K + k0 + kc);
        } else {
            int rb = r - 128;
            cp16(st + TILEB + (uint32_t)(rb * ROWB + kc * 2),
                 B + (size_t)(bn + rb) * K + k0 + kc);
        }
    }
}

template<int BN_T>
__global__ __launch_bounds__(256, 2)
void gemm_mma(const __half* __restrict__ A, const __half* __restrict__ B,
              const float* __restrict__ bias, const float* __restrict__ res,
              float* __restrict__ C, __half* __restrict__ Chf,
              int N, int K, int relu, int qkv,
              const float* __restrict__ bias1, const float* __restrict__ bias2,
              __half* __restrict__ Chf1, __half* __restrict__ Chf2)
{
    constexpr int MT = (BN_T == 128) ? 4 : 2;              // m-frags per warp
    constexpr uint32_t STG = (uint32_t)(128 + BN_T) * ROWB; // stage bytes

    extern __shared__ char smem[];
    const uint32_t sb = smem_u32(smem);
    const int tid = threadIdx.x;
    const int wid = tid >> 5, lane = tid & 31;
    const int wm = (BN_T == 128) ? (wid & 1) : (wid & 3);
    const int wn = (BN_T == 128) ? (wid >> 1) : (wid >> 2);
    const int moff = wm * (16 * MT);
    const int bm = blockIdx.y * 128, bn = blockIdx.x * BN_T;

    float acc[MT][4][4];
#pragma unroll
    for (int mt = 0; mt < MT; mt++)
#pragma unroll
        for (int nt = 0; nt < 4; nt++)
#pragma unroll
            for (int i = 0; i < 4; i++) acc[mt][nt][i] = 0.f;

    const int nk = K / BKG;
    load_stage_t<BN_T>(sb, A, B, bm, bn, 0, K, tid);
    CP_COMMIT();
    load_stage_t<BN_T>(sb + STG, A, B, bm, bn, BKG, K, tid);
    CP_COMMIT();

    for (int ks = 0; ks < nk; ks++) {
        CP_WAIT1();
        __syncthreads();
        if (ks + 2 < nk)
            load_stage_t<BN_T>(sb + ((ks + 2) % 3) * STG, A, B, bm, bn,
                               (ks + 2) * BKG, K, tid);
        CP_COMMIT();

        const uint32_t st = sb + (ks % 3) * STG;
#pragma unroll
        for (int kk = 0; kk < 2; kk++) {
            uint32_t af[MT][4];
            uint32_t aoff = st + (uint32_t)((moff + (lane & 15)) * ROWB)
                          + kk * 32 + ((lane >> 4) & 1) * 16;
#pragma unroll
            for (int mt = 0; mt < MT; mt++)
                LDSM4(af[mt][0], af[mt][1], af[mt][2], af[mt][3], aoff + mt * 16 * ROWB);

            uint32_t bf[4][2];
            uint32_t boff = st + TILEB
                          + (uint32_t)((wn * 32 + (lane & 7) + ((lane >> 4) & 1) * 8) * ROWB)
                          + kk * 32 + ((lane >> 3) & 1) * 16;
#pragma unroll
            for (int np = 0; np < 2; np++) {
                uint32_t r0, r1, r2, r3;
                LDSM4(r0, r1, r2, r3, boff + np * 16 * ROWB);
                bf[2*np][0] = r0; bf[2*np][1] = r1; bf[2*np+1][0] = r2; bf[2*np+1][1] = r3;
            }
#pragma unroll
            for (int mt = 0; mt < MT; mt++)
#pragma unroll
                for (int nt = 0; nt < 4; nt++)
                    MMA16816(acc[mt][nt], af[mt], bf[nt]);
        }
    }
    __syncthreads();

    // ---- epilogue (qkv mode: route by output-column segment) ----
    int bnl = bn, Nol = N;
    const float* bi = bias;
    __half* dst = Chf;
    if (qkv) {
        int seg = bn / 768;
        bnl = bn - seg * 768;
        Nol = 768;
        bi  = (seg == 0) ? bias : (seg == 1) ? bias1 : bias2;
        dst = (seg == 0) ? Chf  : (seg == 1) ? Chf1  : Chf2;
    }

#pragma unroll
    for (int mt = 0; mt < MT; mt++)
#pragma unroll
        for (int nt = 0; nt < 4; nt++) {
            int row = bm + moff + mt * 16 + (lane >> 2);
            int col = bnl + wn * 32 + nt * 8 + (lane & 3) * 2;
            float b0 = bi[col], b1 = bi[col + 1];
#pragma unroll
            for (int half = 0; half < 2; half++) {
                int r = row + half * 8;
                size_t idx = (size_t)r * Nol + col;
                float v0 = acc[mt][nt][half * 2 + 0] + b0;
                float v1 = acc[mt][nt][half * 2 + 1] + b1;
                if (res) {
                    float2 rv = *(const float2*)&res[idx];
                    v0 += rv.x; v1 += rv.y;
                }
                if (relu) { v0 = fmaxf(v0, 0.f); v1 = fmaxf(v1, 0.f); }
                if (C) { float2 o = make_float2(v0, v1); *(float2*)&C[idx] = o; }
                if (dst) *(__half2*)&dst[idx] = __floats2half2_rn(v0, v1);
            }
        }
}

#define GEMM_SMEM_128 (3 * (128 + 128) * ROWB)   // 61440
#define GEMM_SMEM_64  (3 * (128 + 64)  * ROWB)   // 46080

// =================================================================
// Fused weight transpose: all 6 matrices in ONE launch.
// =================================================================
__global__ void wsplit_all(const float* __restrict__ wq, const float* __restrict__ wk,
                           const float* __restrict__ wv, const float* __restrict__ wo,
                           const float* __restrict__ w1, const float* __restrict__ w2,
                           __half* __restrict__ Wd)
{
    __shared__ float t[32][33];
    int bidx = blockIdx.x;
    const float* W; __half* T; int Kd, Nd, kt, nt;
    if (bidx < 2304) {
        int m = bidx / 576, tile = bidx % 576;
        W = (m == 0) ? wq : (m == 1) ? wk : (m == 2) ? wv : wo;
        T = Wd + (size_t)m * 768 * 768;
        Kd = 768; Nd = 768; kt = tile % 24; nt = tile / 24;
    } else if (bidx < 4608) {
        int tile = bidx - 2304;
        W = w1; T = Wd + W1_OFF;
        Kd = 768; Nd = 3072; kt = tile % 24; nt = tile / 24;
    } else {
        int tile = bidx - 4608;
        W = w2; T = Wd + W2_OFF;
        Kd = 3072; Nd = 768; kt = tile % 96; nt = tile / 96;
    }
    int k0 = kt * 32, n0 = nt * 32;
    int tx = threadIdx.x, ty = threadIdx.y;
    for (int i = ty; i < 32; i += 8)
        t[i][tx] = W[(size_t)(k0 + i) * Nd + n0 + tx];
    __syncthreads();
    for (int i = ty; i < 32; i += 8)
        T[(size_t)(n0 + i) * Kd + k0 + tx] = __float2half_rn(t[tx][i]);
}

// activation fp32 -> fp16
__global__ void asplit_kernel(const float* __restrict__ A, __half* __restrict__ Ah)
{
    int i = (blockIdx.x * blockDim.x + threadIdx.x) * 4;
    float4 v = *(const float4*)&A[i];
    *(__half2*)&Ah[i]     = __floats2half2_rn(v.x, v.y);
    *(__half2*)&Ah[i + 2] = __floats2half2_rn(v.z, v.w);
}

// =================================================================
// Flash attention (causal) on mma.sync, pure fp16, fp32 softmax.
// 128 queries x (head,batch); 8 warps; 64-key chunks; 3-stage cp.async ring.
// Occupancy 1 (natural register allocation — occ-2 cap caused regression).
// =================================================================
#define APITCH   144
#define AST_OFF  18432               // Q: 128*144
#define AVH 9216
#define AST_SZ   18432               // K + V tiles
#define ATT_SMEM (AST_OFF + 3 * AST_SZ)   // 73728 B

__device__ __forceinline__ void att_load_kv(
    uint32_t stbase, const __half* Kh, const __half* Vh,
    int b, int h, int j0, int tid)
{
#pragma unroll
    for (int i = 0; i < 4; i++) {
        int idx = tid + i * 256;          // 0..1023
        int t   = idx >> 9;               // 0=K 1=V
        int rem = idx & 511;
        int r   = rem >> 3;               // row 0..63
        int c   = (rem & 7) * 8;
        size_t go = (size_t)(b * TSEQ + j0 + r) * DMODEL + h * DHEAD + c;
        cp16(stbase + t * AVH + r * APITCH + c * 2, (t ? Vh : Kh) + go);
    }
}

__global__ __launch_bounds__(256, 1)
void attn_mma(const __half* __restrict__ Qh,
              const __half* __restrict__ Kh, const __half* __restrict__ Vh,
              __half* __restrict__ Oh)
{
    extern __shared__ char smem[];
    const uint32_t sb = smem_u32(smem);
    const int tid = threadIdx.x;
    const int wid = tid >> 5, lane = tid & 31;
    const int q0 = (gridDim.x - 1 - blockIdx.x) * 128;   // long blocks first
    const int h  = blockIdx.y;
    const int b  = blockIdx.z;

    // ---- load Q tile ----
#pragma unroll
    for (int i = 0; i < 4; i++) {
        int idx = tid + i * 256;
        int r   = idx >> 3;
        int c   = (idx & 7) * 8;
        size_t go = (size_t)(b * TSEQ + q0 + r) * DMODEL + h * DHEAD + c;
        cp16(sb + r * APITCH + c * 2, Qh + go);
    }
    CP_COMMIT();

    const int nch = q0 / 64 + 2;      // >= 2 always
    att_load_kv(sb + AST_OFF, Kh, Vh, b, h, 0, tid);
    CP_COMMIT();
    att_load_kv(sb + AST_OFF + AST_SZ, Kh, Vh, b, h, 64, tid);
    CP_COMMIT();

    float m2[2] = {-1e30f, -1e30f};
    float l2[2] = {0.f, 0.f};
    float o[8][4];
#pragma unroll
    for (int nt = 0; nt < 8; nt++)
#pragma unroll
        for (int i = 0; i < 4; i++) o[nt][i] = 0.f;

    const int r0g = q0 + wid * 16 + (lane >> 2);

    for (int ci = 0; ci < nch; ci++) {
        CP_WAIT1();
        __syncthreads();
        if (ci + 2 < nch)
            att_load_kv(sb + AST_OFF + ((ci + 2) % 3) * AST_SZ,
                        Kh, Vh, b, h, (ci + 2) * 64, tid);
        CP_COMMIT();

        const uint32_t st = sb + AST_OFF + (ci % 3) * AST_SZ;
        const int j0 = ci * 64;

        // ---- S = Q K^T ----
        float s[8][4];
#pragma unroll
        for (int nt = 0; nt < 8; nt++)
#pragma unroll
            for (int i = 0; i < 4; i++) s[nt][i] = 0.f;

#pragma unroll
        for (int kk = 0; kk < 4; kk++) {
            uint32_t qa[4];
            uint32_t aoff = sb + (uint32_t)((wid * 16 + (lane & 15)) * APITCH)
                          + kk * 32 + ((lane >> 4) & 1) * 16;
            LDSM4(qa[0], qa[1], qa[2], qa[3], aoff);
#pragma unroll
            for (int np = 0; np < 4; np++) {
                uint32_t boff = st
                              + (uint32_t)((np * 16 + (lane & 7) + ((lane >> 4) & 1) * 8) * APITCH)
                              + kk * 32 + ((lane >> 3) & 1) * 16;
                uint32_t k0r, k1r, k2r, k3r;
                LDSM4(k0r, k1r, k2r, k3r, boff);
                uint32_t bh0[2] = {k0r, k1r}, bh1[2] = {k2r, k3r};
                MMA16816(s[2*np],   qa, bh0);
                MMA16816(s[2*np+1], qa, bh1);
            }
        }

        // ---- scale + causal mask ----
#pragma unroll
        for (int nt = 0; nt < 8; nt++)
#pragma unroll
            for (int i = 0; i < 4; i++) s[nt][i] *= 0.125f;

        if (j0 >= q0) {
#pragma unroll
            for (int nt = 0; nt < 8; nt++) {
                int col = j0 + nt * 8 + (lane & 3) * 2;
                if (col     > r0g)     s[nt][0] = -1e30f;
                if (col + 1 > r0g)     s[nt][1] = -1e30f;
                if (col     > r0g + 8) s[nt][2] = -1e30f;
                if (col + 1 > r0g + 8) s[nt][3] = -1e30f;
            }
        }

        // ---- streaming softmax ----
#pragma unroll
        for (int rh = 0; rh < 2; rh++) {
            float cm = -1e30f;
#pragma unroll
            for (int nt = 0; nt < 8; nt++)
                cm = fmaxf(cm, fmaxf(s[nt][rh*2], s[nt][rh*2+1]));
            cm = fmaxf(cm, __shfl_xor_sync(0xffffffffu, cm, 1));
            cm = fmaxf(cm, __shfl_xor_sync(0xffffffffu, cm, 2));
            float mn = fmaxf(m2[rh], cm);
            float corr = __expf(m2[rh] - mn);
            m2[rh] = mn;
            float rs = 0.f;
#pragma unroll
            for (int nt = 0; nt < 8; nt++) {
                float p0 = __expf(s[nt][rh*2]   - mn);
                float p1 = __expf(s[nt][rh*2+1] - mn);
                s[nt][rh*2] = p0; s[nt][rh*2+1] = p1;
                rs += p0 + p1;
            }
            rs += __shfl_xor_sync(0xffffffffu, rs, 1);
            rs += __shfl_xor_sync(0xffffffffu, rs, 2);
            l2[rh] = l2[rh] * corr + rs;
#pragma unroll
            for (int nt = 0; nt < 8; nt++) {
                o[nt][rh*2]   *= corr;
                o[nt][rh*2+1] *= corr;
            }
        }

        // ---- O += P V ----
#pragma unroll
        for (int kc = 0; kc < 4; kc++) {
            uint32_t ph[4];
            ph[0] = pack2h(s[2*kc][0],   s[2*kc][1]);
            ph[1] = pack2h(s[2*kc][2],   s[2*kc][3]);
            ph[2] = pack2h(s[2*kc+1][0], s[2*kc+1][1]);
            ph[3] = pack2h(s[2*kc+1][2], s[2*kc+1][3]);
#pragma unroll
            for (int np = 0; np < 4; np++) {
                uint32_t voff = st + AVH
                              + (uint32_t)((kc * 16 + (lane & 15)) * APITCH)
                              + (np * 16 + ((lane >> 4) & 1) * 8) * 2;
                uint32_t v0r, v1r, v2r, v3r;
                LDSM4T(v0r, v1r, v2r, v3r, voff);
                uint32_t vh0[2] = {v0r, v1r}, vh1[2] = {v2r, v3r};
                MMA16816(o[2*np],   ph, vh0);
                MMA16816(o[2*np+1], ph, vh1);
            }
        }
    }

    // ---- normalize + write fp16 ----
    float inv0 = 1.f / l2[0], inv1 = 1.f / l2[1];
#pragma unroll
    for (int nt = 0; nt < 8; nt++) {
        int col = h * DHEAD + nt * 8 + (lane & 3) * 2;
        size_t i0 = (size_t)(b * TSEQ + r0g) * DMODEL + col;
        size_t i1 = (size_t)(b * TSEQ + r0g + 8) * DMODEL + col;
        *(__half2*)&Oh[i0] = __floats2half2_rn(o[nt][0] * inv0, o[nt][1] * inv0);
        *(__half2*)&Oh[i1] = __floats2half2_rn(o[nt][2] * inv1, o[nt][3] * inv1);
    }
}

// =================================================================
// LayerNorm; optionally also emits fp16 of the output.
// =================================================================
__global__ __launch_bounds__(256)
void ln_kernel(const float* __restrict__ in, const float* __restrict__ g,
               const float* __restrict__ be, float* __restrict__ out,
               __half* __restrict__ Oh)
{
    const int row = blockIdx.x;
    const int tid = threadIdx.x;
    const float* xr = in + (size_t)row * DMODEL;

    float v0 = xr[tid], v1 = xr[tid + 256], v2 = xr[tid + 512];
    float s = v0 + v1 + v2;
    float s2 = v0 * v0 + v1 * v1 + v2 * v2;

    __shared__ float rs[8], rs2[8], stats[2];
#pragma unroll
    for (int off = 16; off; off >>= 1) {
        s  += __shfl_xor_sync(0xffffffffu, s,  off);
        s2 += __shfl_xor_sync(0xffffffffu, s2, off);
    }
    int w = tid >> 5, lane = tid & 31;
    if (lane == 0) { rs[w] = s; rs2[w] = s2; }
    __syncthreads();
    if (tid == 0) {
        float S = 0.f, S2 = 0.f;
#pragma unroll
        for (int i = 0; i < 8; i++) { S += rs[i]; S2 += rs2[i]; }
        float mean = S * (1.f / DMODEL);
        float var  = S2 * (1.f / DMODEL) - mean * mean;
        stats[0] = mean;
        stats[1] = rsqrtf(var + 1e-5f);
    }
    __syncthreads();
    float mean = stats[0], r = stats[1];
    size_t rb = (size_t)row * DMODEL;
    float vv[3] = {v0, v1, v2};
#pragma unroll
    for (int p = 0; p < 3; p++) {
        int c = tid + p * 256;
        float y = (vv[p] - mean) * r * g[c] + be[c];
        out[rb + c] = y;
        if (Oh) Oh[rb + c] = __float2half_rn(y);
    }
}

// =================================================================
// Host launch
// =================================================================
extern "C" void kernel_launch(void* const* d_in, const int* in_sizes, int n_in,
                              void* d_out, int out_size)
{
    const float* x  = (const float*)d_in[0];
    const float* wq = (const float*)d_in[1];
    const float* bq = (const float*)d_in[2];
    const float* wk = (const float*)d_in[3];
    const float* bk = (const float*)d_in[4];
    const float* wv = (const float*)d_in[5];
    const float* bv = (const float*)d_in[6];
    const float* wo = (const float*)d_in[7];
    const float* bo = (const float*)d_in[8];
    const float* w1 = (const float*)d_in[9];
    const float* b1 = (const float*)d_in[10];
    const float* w2 = (const float*)d_in[11];
    const float* b2 = (const float*)d_in[12];
    const float* g1 = (const float*)d_in[13];
    const float* be1= (const float*)d_in[14];
    const float* g2 = (const float*)d_in[15];
    const float* be2= (const float*)d_in[16];
    float* out = (float*)d_out;

    float *R1, *H, *R2;
    __half *Qh, *Kh, *Vh, *Act, *FF, *W;
    cudaGetSymbolAddress((void**)&R1,  g_R1);
    cudaGetSymbolAddress((void**)&H,   g_H);
    cudaGetSymbolAddress((void**)&R2,  g_R2);
    cudaGetSymbolAddress((void**)&Qh,  g_qh);
    cudaGetSymbolAddress((void**)&Kh,  g_kh);
    cudaGetSymbolAddress((void**)&Vh,  g_vh);
    cudaGetSymbolAddress((void**)&Act, g_act);
    cudaGetSymbolAddress((void**)&FF,  g_ff);
    cudaGetSymbolAddress((void**)&W,   g_w);

    cudaFuncSetAttribute(attn_mma, cudaFuncAttributeMaxDynamicSharedMemorySize, ATT_SMEM);
    cudaFuncSetAttribute(gemm_mma<128>, cudaFuncAttributeMaxDynamicSharedMemorySize, GEMM_SMEM_128);
    cudaFuncSetAttribute(gemm_mma<64>,  cudaFuncAttributeMaxDynamicSharedMemorySize, GEMM_SMEM_64);

    // all weight transposes in one launch
    wsplit_all<<<6912, dim3(32, 8)>>>(wq, wk, wv, wo, w1, w2, W);

    // x -> fp16
    asplit_kernel<<<MTOK * DMODEL / 1024, 256>>>(x, Act);

    dim3 gQKV((3 * DMODEL) / 128, MTOK / 128);  // (18, 64)
    dim3 gD(DMODEL / 128, MTOK / 128);          // (6, 64)
    dim3 gD64(DMODEL / 64, MTOK / 128);         // (12, 64)
    dim3 gF(DFF / 128,    MTOK / 128);          // (24, 64)

    // fused QKV projection (weights contiguous as [2304][768])
    gemm_mma<128><<<gQKV, 256, GEMM_SMEM_128>>>(Act, W + WQ_OFF, bq, nullptr, nullptr, Qh,
                                                3 * DMODEL, DMODEL, 0, 1, bk, bv, Kh, Vh);

    // causal flash attention -> attn out fp16 into Act
    attn_mma<<<dim3(TSEQ / 128, NHEADS, BBATCH), 256, ATT_SMEM>>>(Qh, Kh, Vh, Act);

    // output projection + residual(x), LN1: BN=64 (cheap A re-read, kills tail)
    gemm_mma<64><<<gD64, 256, GEMM_SMEM_64>>>(Act, W + WO_OFF, bo, x, R1, nullptr,
                                              DMODEL, DMODEL, 0, 0, nullptr, nullptr, nullptr, nullptr);
    ln_kernel<<<MTOK, 256>>>(R1, g1, be1, H, Act);

    // FFN: W1 (+relu) -> FF fp16; W2 at BN=128 (A=FF is 48MB — avoid re-reads)
    gemm_mma<128><<<gF, 256, GEMM_SMEM_128>>>(Act, W + W1_OFF, b1, nullptr, nullptr, FF,
                                              DFF, DMODEL, 1, 0, nullptr, nullptr, nullptr, nullptr);
    gemm_mma<128><<<gD, 256, GEMM_SMEM_128>>>(FF,  W + W2_OFF, b2, H, R2, nullptr,
                                              DMODEL, DFF, 0, 0, nullptr, nullptr, nullptr, nullptr);

    // LN2 -> output
    ln_kernel<<<MTOK, 256>>>(R2, g2, be2, out, nullptr);
}